// round 4
// baseline (speedup 1.0000x reference)
#include <cuda_runtime.h>
#include <cuda_bf16.h>
#include <stdint.h>

#define INPUT_DIM  1024
#define LATENT_DIM 256
#define NUM_EMB    8192
#define BATCH      8192

// ------------------------- device scratch (allocation-free) ----------------
// NOTE: these symbols are ONLY referenced inside __global__ functions.
__device__ float               g_inv_norm[NUM_EMB];
__device__ unsigned int        g_amax[BATCH];
__device__ __align__(16) __nv_bfloat16 g_emb_bf16[NUM_EMB * LATENT_DIM];
__device__ __align__(16) __nv_bfloat16 g_z_bf16[BATCH * LATENT_DIM];
__device__ __align__(16) __nv_bfloat16 g_scores[(size_t)BATCH * NUM_EMB];   // 128 MB

// ------------------------- helpers -----------------------------------------
__device__ __forceinline__ unsigned int float_key(float f) {
    unsigned int u = __float_as_uint(f);
    return (u & 0x80000000u) ? ~u : (u | 0x80000000u);
}
__device__ __forceinline__ void mma_bf16(float* d, const uint32_t* a, const uint32_t* b) {
    asm volatile(
        "mma.sync.aligned.m16n8k16.row.col.f32.bf16.bf16.f32 "
        "{%0,%1,%2,%3}, {%4,%5,%6,%7}, {%8,%9}, {%0,%1,%2,%3};"
        : "+f"(d[0]), "+f"(d[1]), "+f"(d[2]), "+f"(d[3])
        : "r"(a[0]), "r"(a[1]), "r"(a[2]), "r"(a[3]), "r"(b[0]), "r"(b[1]));
}

// ---------------------------------------------------------------------------
// init: inv-norms + emb->bf16 + amax reset (all via in-kernel symbol access)
// ---------------------------------------------------------------------------
__global__ void init_kernel(const float* __restrict__ emb) {
    int i = blockIdx.x * blockDim.x + threadIdx.x;
    if (i < NUM_EMB) {
        const float4* p = reinterpret_cast<const float4*>(emb + (size_t)i * LATENT_DIM);
        unsigned int* dst = reinterpret_cast<unsigned int*>(g_emb_bf16 + (size_t)i * LATENT_DIM);
        float s = 0.0f;
        #pragma unroll 8
        for (int j = 0; j < LATENT_DIM / 4; j++) {
            float4 v = p[j];
            s += v.x * v.x + v.y * v.y + v.z * v.z + v.w * v.w;
            __nv_bfloat162 h0 = __floats2bfloat162_rn(v.x, v.y);
            __nv_bfloat162 h1 = __floats2bfloat162_rn(v.z, v.w);
            dst[j * 2 + 0] = *reinterpret_cast<unsigned int*>(&h0);
            dst[j * 2 + 1] = *reinterpret_cast<unsigned int*>(&h1);
        }
        g_inv_norm[i] = 1.0f / sqrtf(s);
    }
    if (i < BATCH) g_amax[i] = 0u;
}

// z (fp32, external ptr) -> g_z_bf16 (symbol, in-kernel)
__global__ void convert_z_kernel(const float* __restrict__ z) {
    int i = blockIdx.x * blockDim.x + threadIdx.x;   // 262144 threads x 8 elems
    const float4* s4 = reinterpret_cast<const float4*>(z) + (size_t)i * 2;
    float4 a = s4[0], b = s4[1];
    uint4 o; __nv_bfloat162 h;
    h = __floats2bfloat162_rn(a.x, a.y); o.x = *reinterpret_cast<unsigned int*>(&h);
    h = __floats2bfloat162_rn(a.z, a.w); o.y = *reinterpret_cast<unsigned int*>(&h);
    h = __floats2bfloat162_rn(b.x, b.y); o.z = *reinterpret_cast<unsigned int*>(&h);
    h = __floats2bfloat162_rn(b.z, b.w); o.w = *reinterpret_cast<unsigned int*>(&h);
    reinterpret_cast<uint4*>(g_z_bf16)[i] = o;
}

// ---------------------------------------------------------------------------
// fp32 SIMT GEMM (encoder + decoder): C = A[M,K] @ B[N,K]^T + bias
// ---------------------------------------------------------------------------
constexpr int BM = 128, BN = 128, BK = 16, TM = 8, TN = 8;
constexpr int BMP = 132;
constexpr int NTHREADS = 256;

__device__ __forceinline__ void load_tile(const float* __restrict__ src, int ld,
                                          int row0, int k0,
                                          float* __restrict__ dst, int tid) {
    #pragma unroll
    for (int it = 0; it < 2; it++) {
        int idx = tid + it * NTHREADS;
        int r   = idx >> 2;
        int kq  = (idx & 3) * 4;
        float4 v = *reinterpret_cast<const float4*>(&src[(size_t)(row0 + r) * ld + k0 + kq]);
        dst[(kq + 0) * BMP + r] = v.x;
        dst[(kq + 1) * BMP + r] = v.y;
        dst[(kq + 2) * BMP + r] = v.z;
        dst[(kq + 3) * BMP + r] = v.w;
    }
}

__global__ void __launch_bounds__(NTHREADS)
sgemm_abT_bias(const float* __restrict__ A, const float* __restrict__ B,
               const float* __restrict__ bias, float* __restrict__ C,
               int M, int N, int K) {
    __shared__ __align__(16) float As[BK * BMP];
    __shared__ __align__(16) float Bs[BK * BMP];
    const int tid  = threadIdx.x;
    const int tx   = tid & 15;
    const int ty   = tid >> 4;
    const int row0 = blockIdx.y * BM;
    const int col0 = blockIdx.x * BN;
    float acc[TM][TN] = {};
    for (int k0 = 0; k0 < K; k0 += BK) {
        load_tile(A, K, row0, k0, As, tid);
        load_tile(B, K, col0, k0, Bs, tid);
        __syncthreads();
        #pragma unroll
        for (int kk = 0; kk < BK; kk++) {
            float rm[TM], rn[TN];
            float4 a0 = *reinterpret_cast<const float4*>(&As[kk * BMP + ty * TM]);
            float4 a1 = *reinterpret_cast<const float4*>(&As[kk * BMP + ty * TM + 4]);
            float4 b0 = *reinterpret_cast<const float4*>(&Bs[kk * BMP + tx * TN]);
            float4 b1 = *reinterpret_cast<const float4*>(&Bs[kk * BMP + tx * TN + 4]);
            rm[0]=a0.x; rm[1]=a0.y; rm[2]=a0.z; rm[3]=a0.w;
            rm[4]=a1.x; rm[5]=a1.y; rm[6]=a1.z; rm[7]=a1.w;
            rn[0]=b0.x; rn[1]=b0.y; rn[2]=b0.z; rn[3]=b0.w;
            rn[4]=b1.x; rn[5]=b1.y; rn[6]=b1.z; rn[7]=b1.w;
            #pragma unroll
            for (int m = 0; m < TM; m++)
                #pragma unroll
                for (int n = 0; n < TN; n++)
                    acc[m][n] = fmaf(rm[m], rn[n], acc[m][n]);
        }
        __syncthreads();
    }
    #pragma unroll
    for (int m = 0; m < TM; m++) {
        int r = row0 + ty * TM + m;
        #pragma unroll
        for (int n = 0; n < TN; n += 4) {
            int c = col0 + tx * TN + n;
            float4 v;
            v.x = acc[m][n + 0] + bias[c + 0];
            v.y = acc[m][n + 1] + bias[c + 1];
            v.z = acc[m][n + 2] + bias[c + 2];
            v.w = acc[m][n + 3] + bias[c + 3];
            *reinterpret_cast<float4*>(&C[(size_t)r * N + c]) = v;
        }
    }
}

// ---------------------------------------------------------------------------
// HMMA bf16 score GEMM with direct-LDS fragment loads (no ldmatrix).
// CTA 128x128, 8 warps (4M x 2N), warp tile 32x64. K in 4 chunks of 64.
// Fragment maps (PTX mma.m16n8k16, g=lane>>2, q=lane&3):
//   a0=A[g][2q,2q+1]  a1=A[g+8][..]  a2=A[g][2q+8,..]  a3=A[g+8][2q+8,..]
//   b0=E[g][2q,2q+1]  b1=E[g][2q+8,2q+9]          (E row-major [n][k] = B col-major)
//   c0,c1=(g, 2q..)   c2,c3=(g+8, 2q..)
// ---------------------------------------------------------------------------
constexpr int SKH = 72;   // bf16 smem row stride: 144B -> conflict-free frags

__device__ __forceinline__ void hmma_load_chunk(const __nv_bfloat16* __restrict__ g,
                                                int gr0, int k0, __nv_bfloat16* sm, int tid) {
    #pragma unroll
    for (int it = 0; it < 4; it++) {
        int idx = tid + it * 256;      // 0..1023
        int r   = idx >> 3;            // 0..127
        int c   = idx & 7;             // 16B chunk
        *reinterpret_cast<uint4*>(&sm[r * SKH + c * 8]) =
            *reinterpret_cast<const uint4*>(g + (size_t)(gr0 + r) * 256 + k0 + c * 8);
    }
}

__global__ void __launch_bounds__(256)
hmma_scores_kernel() {
    __shared__ __align__(16) __nv_bfloat16 sA[128 * SKH];
    __shared__ __align__(16) __nv_bfloat16 sB[128 * SKH];
    __shared__ float s_inv[128];
    __shared__ unsigned int s_amax[128];

    const int tid = threadIdx.x, wid = tid >> 5, lane = tid & 31;
    const int row0 = blockIdx.y * 128, col0 = blockIdx.x * 128;
    const int wm = (wid & 3) * 32, wn = (wid >> 2) * 64;
    const int g = lane >> 2, q = lane & 3;

    if (tid < 128) { s_inv[tid] = g_inv_norm[col0 + tid]; s_amax[tid] = 0u; }

    float acc[2][8][4] = {};
    #pragma unroll
    for (int kc = 0; kc < 4; kc++) {
        hmma_load_chunk(g_z_bf16, row0, kc * 64, sA, tid);
        hmma_load_chunk(g_emb_bf16, col0, kc * 64, sB, tid);
        __syncthreads();
        #pragma unroll
        for (int k16 = 0; k16 < 4; k16++) {
            const int koff = k16 * 16 + q * 2;
            uint32_t a[2][4];
            #pragma unroll
            for (int mf = 0; mf < 2; mf++) {
                const __nv_bfloat16* base = &sA[(wm + mf * 16 + g) * SKH + koff];
                a[mf][0] = *reinterpret_cast<const uint32_t*>(base);
                a[mf][1] = *reinterpret_cast<const uint32_t*>(base + 8 * SKH);
                a[mf][2] = *reinterpret_cast<const uint32_t*>(base + 8);
                a[mf][3] = *reinterpret_cast<const uint32_t*>(base + 8 * SKH + 8);
            }
            uint32_t b[8][2];
            #pragma unroll
            for (int nf = 0; nf < 8; nf++) {
                const __nv_bfloat16* nb = &sB[(wn + nf * 8 + g) * SKH + koff];
                b[nf][0] = *reinterpret_cast<const uint32_t*>(nb);
                b[nf][1] = *reinterpret_cast<const uint32_t*>(nb + 8);
            }
            #pragma unroll
            for (int mf = 0; mf < 2; mf++)
                #pragma unroll
                for (int nf = 0; nf < 8; nf++)
                    mma_bf16(acc[mf][nf], a[mf], b[nf]);
        }
        __syncthreads();
    }

    // epilogue: scale by inv_norm, store bf16 scores, per-row approx max keys
    #pragma unroll
    for (int mf = 0; mf < 2; mf++) {
        #pragma unroll
        for (int rp = 0; rp < 2; rp++) {
            int lrow = wm + mf * 16 + g + rp * 8;
            int grow = row0 + lrow;
            unsigned int bestk = 0u;
            unsigned int* out = reinterpret_cast<unsigned int*>(
                g_scores + (size_t)grow * NUM_EMB + col0);
            #pragma unroll
            for (int nf = 0; nf < 8; nf++) {
                int lcol = wn + nf * 8 + q * 2;
                float s0 = acc[mf][nf][rp * 2 + 0] * s_inv[lcol + 0];
                float s1 = acc[mf][nf][rp * 2 + 1] * s_inv[lcol + 1];
                unsigned int k0 = float_key(s0), k1 = float_key(s1);
                bestk = bestk > k0 ? bestk : k0;
                bestk = bestk > k1 ? bestk : k1;
                __nv_bfloat162 h = __floats2bfloat162_rn(s0, s1);
                out[lcol >> 1] = *reinterpret_cast<unsigned int*>(&h);
            }
            atomicMax(&s_amax[lrow], bestk);
        }
    }
    __syncthreads();
    if (tid < 128) atomicMax(&g_amax[row0 + tid], s_amax[tid]);
}

// ---------------------------------------------------------------------------
// select + exact fp32 rescore + gather (robust: NaN-proof, clamped)
// ---------------------------------------------------------------------------
__global__ void __launch_bounds__(256)
select_gather_kernel(const float* __restrict__ z, const float* __restrict__ emb,
                     float* __restrict__ zq_out, float* __restrict__ idx_out) {
    const int row = blockIdx.x;
    const int tid = threadIdx.x;
    __shared__ __align__(16) float s_z[256];
    __shared__ unsigned long long red[256];

    s_z[tid] = z[(size_t)row * LATENT_DIM + tid];
    unsigned int mk = g_amax[row];
    float maxf = (mk & 0x80000000u) ? __uint_as_float(mk ^ 0x80000000u)
                                    : __uint_as_float(~mk);
    float thresh = maxf - 0.01f;
    // cosine scores live in [-1,1]; anything else (NaN/Inf/garbage) -> full scan
    if (!(thresh >= -4.0f) || !(thresh <= 1.0f)) thresh = -4.0f;
    __syncthreads();

    unsigned long long best = 0ull;
    const uint4* srow = reinterpret_cast<const uint4*>(g_scores + (size_t)row * NUM_EMB);
    #pragma unroll
    for (int it = 0; it < 4; it++) {
        int j = tid + it * 256;
        uint4 v = srow[j];
        const unsigned int w[4] = {v.x, v.y, v.z, v.w};
        #pragma unroll
        for (int qq = 0; qq < 4; qq++) {
            __nv_bfloat162 h = *reinterpret_cast<const __nv_bfloat162*>(&w[qq]);
            float f0 = __bfloat162float(h.x);
            float f1 = __bfloat162float(h.y);
            #pragma unroll
            for (int s = 0; s < 2; s++) {
                float f = s ? f1 : f0;
                if (!(f < thresh)) {               // NaN score also rescored
                    int k = j * 8 + qq * 2 + s;
                    const float4* e = reinterpret_cast<const float4*>(emb + (size_t)k * LATENT_DIM);
                    const float4* zz = reinterpret_cast<const float4*>(s_z);
                    float dot = 0.0f;
                    #pragma unroll 16
                    for (int q2 = 0; q2 < LATENT_DIM / 4; q2++) {
                        float4 ev = e[q2], zv = zz[q2];
                        dot += ev.x * zv.x + ev.y * zv.y + ev.z * zv.z + ev.w * zv.w;
                    }
                    float cosv = dot * g_inv_norm[k];
                    unsigned long long key =
                        ((unsigned long long)float_key(cosv) << 32) |
                        (unsigned long long)(0xFFFFFFFFu - (unsigned)k);
                    best = best > key ? best : key;
                }
            }
        }
    }
    red[tid] = best;
    __syncthreads();
    #pragma unroll
    for (int s = 128; s > 0; s >>= 1) {
        if (tid < s) {
            unsigned long long o = red[tid + s];
            if (o > red[tid]) red[tid] = o;
        }
        __syncthreads();
    }
    unsigned int widx = 0xFFFFFFFFu - (unsigned int)(red[0] & 0xFFFFFFFFull);
    if (widx >= NUM_EMB) widx = 0;   // never wild-read
    if (tid == 0) idx_out[row] = (float)widx;
    if (tid < 64) {
        reinterpret_cast<float4*>(zq_out + (size_t)row * LATENT_DIM)[tid] =
            reinterpret_cast<const float4*>(emb + (size_t)widx * LATENT_DIM)[tid];
    }
}

// ---------------------------------------------------------------------------
// launch
// ---------------------------------------------------------------------------
extern "C" void kernel_launch(void* const* d_in, const int* in_sizes, int n_in,
                              void* d_out, int out_size) {
    const float* x     = (const float*)d_in[0];
    const float* enc_w = (const float*)d_in[1];
    const float* enc_b = (const float*)d_in[2];
    const float* emb   = (const float*)d_in[3];
    const float* dec_w = (const float*)d_in[4];
    const float* dec_b = (const float*)d_in[5];

    float* out     = (float*)d_out;
    float* x_recon = out;
    float* z       = x_recon + (size_t)BATCH * INPUT_DIM;
    float* zq      = z + (size_t)BATCH * LATENT_DIM;
    float* idxf    = zq + (size_t)BATCH * LATENT_DIM;

    // 0) inv-norms + emb bf16 + amax reset
    init_kernel<<<(NUM_EMB + 255) / 256, 256>>>(emb);

    // 1) encoder (fp32 SIMT): z = x @ enc_w^T + enc_b
    sgemm_abT_bias<<<dim3(LATENT_DIM / BN, BATCH / BM), NTHREADS>>>(
        x, enc_w, enc_b, z, BATCH, LATENT_DIM, INPUT_DIM);

    // 2) z -> bf16 (symbol written in-kernel)
    convert_z_kernel<<<(BATCH * LATENT_DIM / 8) / 256, 256>>>(z);

    // 3) HMMA bf16 approximate cosine scores + per-row approx max
    hmma_scores_kernel<<<dim3(NUM_EMB / 128, BATCH / 128), 256>>>();

    // 4) candidate select + exact fp32 rescore + argmin + gather
    select_gather_kernel<<<BATCH, 256>>>(z, emb, zq, idxf);

    // 5) decoder (fp32 SIMT): x_recon = z_q @ dec_w^T + dec_b
    sgemm_abT_bias<<<dim3(INPUT_DIM / BN, BATCH / BM), NTHREADS>>>(
        zq, dec_w, dec_b, x_recon, BATCH, INPUT_DIM, LATENT_DIM);
}

// round 5
// speedup vs baseline: 2.5188x; 2.5188x over previous
#include <cuda_runtime.h>
#include <cuda_bf16.h>
#include <stdint.h>

#define INPUT_DIM  1024
#define LATENT_DIM 256
#define NUM_EMB    8192
#define BATCH      8192

// ------------------------- device scratch (allocation-free) ----------------
// NOTE: symbols only referenced inside __global__ functions.
__device__ float               g_inv_norm[NUM_EMB];
__device__ unsigned int        g_amax[BATCH];
__device__ __align__(16) __nv_bfloat16 g_emb_bf16[NUM_EMB * LATENT_DIM];
__device__ __align__(16) __nv_bfloat16 g_z_bf16[BATCH * LATENT_DIM];
__device__ __align__(16) __nv_bfloat16 g_scores[(size_t)BATCH * NUM_EMB];   // 128 MB

// ------------------------- helpers -----------------------------------------
__device__ __forceinline__ unsigned int float_key(float f) {
    unsigned int u = __float_as_uint(f);
    return (u & 0x80000000u) ? ~u : (u | 0x80000000u);
}
__device__ __forceinline__ void mma_bf16(float* d, const uint32_t* a, const uint32_t* b) {
    asm volatile(
        "mma.sync.aligned.m16n8k16.row.col.f32.bf16.bf16.f32 "
        "{%0,%1,%2,%3}, {%4,%5,%6,%7}, {%8,%9}, {%0,%1,%2,%3};"
        : "+f"(d[0]), "+f"(d[1]), "+f"(d[2]), "+f"(d[3])
        : "r"(a[0]), "r"(a[1]), "r"(a[2]), "r"(a[3]), "r"(b[0]), "r"(b[1]));
}
__device__ __forceinline__ unsigned int pack_bf16x2(float lo, float hi) {
    __nv_bfloat162 h = __floats2bfloat162_rn(lo, hi);
    return *reinterpret_cast<unsigned int*>(&h);
}

// ---------------------------------------------------------------------------
// init: warp-per-row; emb->bf16 (coalesced), inv-norm via warp reduce, amax=0
// ---------------------------------------------------------------------------
__global__ void __launch_bounds__(256)
init_kernel(const float* __restrict__ emb) {
    const int warp = threadIdx.x >> 5, lane = threadIdx.x & 31;
    const int row  = blockIdx.x * 8 + warp;            // grid = 1024 -> rows 0..8191
    const float4* p = reinterpret_cast<const float4*>(emb + (size_t)row * LATENT_DIM);
    float4 a = p[lane * 2], b = p[lane * 2 + 1];
    uint4 o;
    o.x = pack_bf16x2(a.x, a.y); o.y = pack_bf16x2(a.z, a.w);
    o.z = pack_bf16x2(b.x, b.y); o.w = pack_bf16x2(b.z, b.w);
    *reinterpret_cast<uint4*>(g_emb_bf16 + (size_t)row * LATENT_DIM + lane * 8) = o;
    float s = a.x*a.x + a.y*a.y + a.z*a.z + a.w*a.w
            + b.x*b.x + b.y*b.y + b.z*b.z + b.w*b.w;
    #pragma unroll
    for (int off = 16; off > 0; off >>= 1) s += __shfl_xor_sync(0xFFFFFFFFu, s, off);
    if (lane == 0) {
        g_inv_norm[row] = rsqrtf(s);
        g_amax[row] = 0u;                              // NUM_EMB == BATCH == 8192
    }
}

// z (fp32 ptr) -> g_z_bf16 (symbol, in-kernel)
__global__ void convert_z_kernel(const float* __restrict__ z) {
    int i = blockIdx.x * blockDim.x + threadIdx.x;
    const float4* s4 = reinterpret_cast<const float4*>(z) + (size_t)i * 2;
    float4 a = s4[0], b = s4[1];
    uint4 o;
    o.x = pack_bf16x2(a.x, a.y); o.y = pack_bf16x2(a.z, a.w);
    o.z = pack_bf16x2(b.x, b.y); o.w = pack_bf16x2(b.z, b.w);
    reinterpret_cast<uint4*>(g_z_bf16)[i] = o;
}

// ---------------------------------------------------------------------------
// fp32 SIMT GEMM (encoder + decoder): C = A[M,K] @ B[N,K]^T + bias
// ---------------------------------------------------------------------------
constexpr int BM = 128, BN = 128, BK = 16, TM = 8, TN = 8;
constexpr int BMP = 132;
constexpr int NTHREADS = 256;

__device__ __forceinline__ void load_tile(const float* __restrict__ src, int ld,
                                          int row0, int k0,
                                          float* __restrict__ dst, int tid) {
    #pragma unroll
    for (int it = 0; it < 2; it++) {
        int idx = tid + it * NTHREADS;
        int r   = idx >> 2;
        int kq  = (idx & 3) * 4;
        float4 v = *reinterpret_cast<const float4*>(&src[(size_t)(row0 + r) * ld + k0 + kq]);
        dst[(kq + 0) * BMP + r] = v.x;
        dst[(kq + 1) * BMP + r] = v.y;
        dst[(kq + 2) * BMP + r] = v.z;
        dst[(kq + 3) * BMP + r] = v.w;
    }
}

__global__ void __launch_bounds__(NTHREADS)
sgemm_abT_bias(const float* __restrict__ A, const float* __restrict__ B,
               const float* __restrict__ bias, float* __restrict__ C,
               int M, int N, int K) {
    __shared__ __align__(16) float As[BK * BMP];
    __shared__ __align__(16) float Bs[BK * BMP];
    const int tid  = threadIdx.x;
    const int tx   = tid & 15;
    const int ty   = tid >> 4;
    const int row0 = blockIdx.y * BM;
    const int col0 = blockIdx.x * BN;
    float acc[TM][TN] = {};
    for (int k0 = 0; k0 < K; k0 += BK) {
        load_tile(A, K, row0, k0, As, tid);
        load_tile(B, K, col0, k0, Bs, tid);
        __syncthreads();
        #pragma unroll
        for (int kk = 0; kk < BK; kk++) {
            float rm[TM], rn[TN];
            float4 a0 = *reinterpret_cast<const float4*>(&As[kk * BMP + ty * TM]);
            float4 a1 = *reinterpret_cast<const float4*>(&As[kk * BMP + ty * TM + 4]);
            float4 b0 = *reinterpret_cast<const float4*>(&Bs[kk * BMP + tx * TN]);
            float4 b1 = *reinterpret_cast<const float4*>(&Bs[kk * BMP + tx * TN + 4]);
            rm[0]=a0.x; rm[1]=a0.y; rm[2]=a0.z; rm[3]=a0.w;
            rm[4]=a1.x; rm[5]=a1.y; rm[6]=a1.z; rm[7]=a1.w;
            rn[0]=b0.x; rn[1]=b0.y; rn[2]=b0.z; rn[3]=b0.w;
            rn[4]=b1.x; rn[5]=b1.y; rn[6]=b1.z; rn[7]=b1.w;
            #pragma unroll
            for (int m = 0; m < TM; m++)
                #pragma unroll
                for (int n = 0; n < TN; n++)
                    acc[m][n] = fmaf(rm[m], rn[n], acc[m][n]);
        }
        __syncthreads();
    }
    #pragma unroll
    for (int m = 0; m < TM; m++) {
        int r = row0 + ty * TM + m;
        #pragma unroll
        for (int n = 0; n < TN; n += 4) {
            int c = col0 + tx * TN + n;
            float4 v;
            v.x = acc[m][n + 0] + bias[c + 0];
            v.y = acc[m][n + 1] + bias[c + 1];
            v.z = acc[m][n + 2] + bias[c + 2];
            v.w = acc[m][n + 3] + bias[c + 3];
            *reinterpret_cast<float4*>(&C[(size_t)r * N + c]) = v;
        }
    }
}

// ---------------------------------------------------------------------------
// HMMA bf16 score GEMM (direct-LDS fragments). CTA 128x128, 8 warps, K chunks 64.
// ---------------------------------------------------------------------------
constexpr int SKH = 72;

__device__ __forceinline__ void hmma_load_chunk(const __nv_bfloat16* __restrict__ g,
                                                int gr0, int k0, __nv_bfloat16* sm, int tid) {
    #pragma unroll
    for (int it = 0; it < 4; it++) {
        int idx = tid + it * 256;
        int r   = idx >> 3;
        int c   = idx & 7;
        *reinterpret_cast<uint4*>(&sm[r * SKH + c * 8]) =
            *reinterpret_cast<const uint4*>(g + (size_t)(gr0 + r) * 256 + k0 + c * 8);
    }
}

__global__ void __launch_bounds__(256)
hmma_scores_kernel() {
    __shared__ __align__(16) __nv_bfloat16 sA[128 * SKH];
    __shared__ __align__(16) __nv_bfloat16 sB[128 * SKH];
    __shared__ float s_inv[128];
    __shared__ unsigned int s_amax[128];

    const int tid = threadIdx.x, wid = tid >> 5, lane = tid & 31;
    const int row0 = blockIdx.y * 128, col0 = blockIdx.x * 128;
    const int wm = (wid & 3) * 32, wn = (wid >> 2) * 64;
    const int g = lane >> 2, q = lane & 3;

    if (tid < 128) { s_inv[tid] = g_inv_norm[col0 + tid]; s_amax[tid] = 0u; }

    float acc[2][8][4] = {};
    #pragma unroll
    for (int kc = 0; kc < 4; kc++) {
        hmma_load_chunk(g_z_bf16, row0, kc * 64, sA, tid);
        hmma_load_chunk(g_emb_bf16, col0, kc * 64, sB, tid);
        __syncthreads();
        #pragma unroll
        for (int k16 = 0; k16 < 4; k16++) {
            const int koff = k16 * 16 + q * 2;
            uint32_t a[2][4];
            #pragma unroll
            for (int mf = 0; mf < 2; mf++) {
                const __nv_bfloat16* base = &sA[(wm + mf * 16 + g) * SKH + koff];
                a[mf][0] = *reinterpret_cast<const uint32_t*>(base);
                a[mf][1] = *reinterpret_cast<const uint32_t*>(base + 8 * SKH);
                a[mf][2] = *reinterpret_cast<const uint32_t*>(base + 8);
                a[mf][3] = *reinterpret_cast<const uint32_t*>(base + 8 * SKH + 8);
            }
            uint32_t b[8][2];
            #pragma unroll
            for (int nf = 0; nf < 8; nf++) {
                const __nv_bfloat16* nb = &sB[(wn + nf * 8 + g) * SKH + koff];
                b[nf][0] = *reinterpret_cast<const uint32_t*>(nb);
                b[nf][1] = *reinterpret_cast<const uint32_t*>(nb + 8);
            }
            #pragma unroll
            for (int mf = 0; mf < 2; mf++)
                #pragma unroll
                for (int nf = 0; nf < 8; nf++)
                    mma_bf16(acc[mf][nf], a[mf], b[nf]);
        }
        __syncthreads();
    }

    #pragma unroll
    for (int mf = 0; mf < 2; mf++) {
        #pragma unroll
        for (int rp = 0; rp < 2; rp++) {
            int lrow = wm + mf * 16 + g + rp * 8;
            int grow = row0 + lrow;
            unsigned int bestk = 0u;
            unsigned int* out = reinterpret_cast<unsigned int*>(
                g_scores + (size_t)grow * NUM_EMB + col0);
            #pragma unroll
            for (int nf = 0; nf < 8; nf++) {
                int lcol = wn + nf * 8 + q * 2;
                float s0 = acc[mf][nf][rp * 2 + 0] * s_inv[lcol + 0];
                float s1 = acc[mf][nf][rp * 2 + 1] * s_inv[lcol + 1];
                unsigned int k0 = float_key(s0), k1 = float_key(s1);
                bestk = bestk > k0 ? bestk : k0;
                bestk = bestk > k1 ? bestk : k1;
                out[lcol >> 1] = pack_bf16x2(s0, s1);
            }
            atomicMax(&s_amax[lrow], bestk);
        }
    }
    __syncthreads();
    if (tid < 128) atomicMax(&g_amax[row0 + tid], s_amax[tid]);
}

// ---------------------------------------------------------------------------
// select: warp-per-row, rolled scan, warp-cooperative exact rescore + gather
// ---------------------------------------------------------------------------
__global__ void __launch_bounds__(256)
select_gather_kernel(const float* __restrict__ z, const float* __restrict__ emb,
                     float* __restrict__ zq_out, float* __restrict__ idx_out) {
    const int warp = threadIdx.x >> 5, lane = threadIdx.x & 31;
    const int row  = blockIdx.x * 8 + warp;

    // per-lane z fragment: elems [lane*8, lane*8+8)
    const float4* zrow = reinterpret_cast<const float4*>(z + (size_t)row * LATENT_DIM);
    float4 zf0 = zrow[lane * 2], zf1 = zrow[lane * 2 + 1];

    unsigned int mk = g_amax[row];
    float maxf = (mk & 0x80000000u) ? __uint_as_float(mk ^ 0x80000000u)
                                    : __uint_as_float(~mk);
    float thresh = maxf - 0.01f;
    if (!(thresh >= -4.0f) || !(thresh <= 1.0f)) thresh = -4.0f;   // NaN/garbage -> full scan

    unsigned long long best = 0ull;
    const uint4* srow = reinterpret_cast<const uint4*>(g_scores + (size_t)row * NUM_EMB);

    for (int it = 0; it < 32; it++) {                 // 32 x (32 lanes x 8 scores)
        uint4 v = srow[it * 32 + lane];
        unsigned int w[4] = {v.x, v.y, v.z, v.w};
        unsigned int cmask = 0;
        #pragma unroll
        for (int qq = 0; qq < 4; qq++) {
            __nv_bfloat162 h = *reinterpret_cast<__nv_bfloat162*>(&w[qq]);
            if (!(__bfloat162float(h.x) < thresh)) cmask |= 1u << (2 * qq);
            if (!(__bfloat162float(h.y) < thresh)) cmask |= 1u << (2 * qq + 1);
        }
        unsigned int lmask = __ballot_sync(0xFFFFFFFFu, cmask != 0);
        while (lmask) {                                // rare: ~2 candidates per row total
            int src = __ffs(lmask) - 1; lmask &= lmask - 1;
            unsigned int cm = __shfl_sync(0xFFFFFFFFu, cmask, src);
            while (cm) {
                int j = __ffs(cm) - 1; cm &= cm - 1;
                int k = it * 256 + src * 8 + j;
                // warp-cooperative exact fp32 dot
                const float4* e = reinterpret_cast<const float4*>(emb + (size_t)k * LATENT_DIM);
                float4 e0 = e[lane * 2], e1 = e[lane * 2 + 1];
                float d = e0.x*zf0.x + e0.y*zf0.y + e0.z*zf0.z + e0.w*zf0.w
                        + e1.x*zf1.x + e1.y*zf1.y + e1.z*zf1.z + e1.w*zf1.w;
                #pragma unroll
                for (int off = 16; off > 0; off >>= 1)
                    d += __shfl_xor_sync(0xFFFFFFFFu, d, off);
                float cosv = d * g_inv_norm[k];        // identical on all lanes
                unsigned long long key =
                    ((unsigned long long)float_key(cosv) << 32) |
                    (unsigned long long)(0xFFFFFFFFu - (unsigned)k);
                best = best > key ? best : key;
            }
        }
    }
    unsigned int widx = 0xFFFFFFFFu - (unsigned int)(best & 0xFFFFFFFFull);
    if (widx >= NUM_EMB) widx = 0;                     // never wild-read
    if (lane == 0) idx_out[row] = (float)widx;
    const float4* e = reinterpret_cast<const float4*>(emb + (size_t)widx * LATENT_DIM);
    float4* dst = reinterpret_cast<float4*>(zq_out + (size_t)row * LATENT_DIM);
    dst[lane * 2]     = e[lane * 2];
    dst[lane * 2 + 1] = e[lane * 2 + 1];
}

// ---------------------------------------------------------------------------
// launch
// ---------------------------------------------------------------------------
extern "C" void kernel_launch(void* const* d_in, const int* in_sizes, int n_in,
                              void* d_out, int out_size) {
    const float* x     = (const float*)d_in[0];
    const float* enc_w = (const float*)d_in[1];
    const float* enc_b = (const float*)d_in[2];
    const float* emb   = (const float*)d_in[3];
    const float* dec_w = (const float*)d_in[4];
    const float* dec_b = (const float*)d_in[5];

    float* out     = (float*)d_out;
    float* x_recon = out;
    float* z       = x_recon + (size_t)BATCH * INPUT_DIM;
    float* zq      = z + (size_t)BATCH * LATENT_DIM;
    float* idxf    = zq + (size_t)BATCH * LATENT_DIM;

    // 0) inv-norms + emb bf16 + amax reset
    init_kernel<<<NUM_EMB / 8, 256>>>(emb);

    // 1) encoder (fp32 SIMT): z = x @ enc_w^T + enc_b
    sgemm_abT_bias<<<dim3(LATENT_DIM / BN, BATCH / BM), NTHREADS>>>(
        x, enc_w, enc_b, z, BATCH, LATENT_DIM, INPUT_DIM);

    // 2) z -> bf16
    convert_z_kernel<<<(BATCH * LATENT_DIM / 8) / 256, 256>>>(z);

    // 3) HMMA bf16 approximate cosine scores + per-row approx max
    hmma_scores_kernel<<<dim3(NUM_EMB / 128, BATCH / 128), 256>>>();

    // 4) candidate select + exact fp32 rescore + argmin + gather
    select_gather_kernel<<<BATCH / 8, 256>>>(z, emb, zq, idxf);

    // 5) decoder (fp32 SIMT): x_recon = z_q @ dec_w^T + dec_b
    sgemm_abT_bias<<<dim3(INPUT_DIM / BN, BATCH / BM), NTHREADS>>>(
        zq, dec_w, dec_b, x_recon, BATCH, INPUT_DIM, LATENT_DIM);
}

// round 6
// speedup vs baseline: 32.4430x; 12.8805x over previous
#include <cuda_runtime.h>
#include <cuda_bf16.h>
#include <stdint.h>

#define INPUT_DIM  1024
#define LATENT_DIM 256
#define NUM_EMB    8192
#define BATCH      8192

#define MARGIN 0.02f

// ------------------------- device scratch (allocation-free) ----------------
// NOTE: symbols only referenced inside __global__ functions.
__device__ float               g_inv_norm[NUM_EMB];
__device__ float               g_zinv[BATCH];
__device__ unsigned int        g_amax[BATCH];
__device__ __align__(16) __nv_bfloat16 g_emb_bf16[NUM_EMB * LATENT_DIM];
__device__ __align__(16) __nv_bfloat16 g_z_bf16[BATCH * LATENT_DIM];
__device__ __align__(16) __nv_bfloat16 g_scores[(size_t)BATCH * NUM_EMB];   // 128 MB

// ------------------------- helpers -----------------------------------------
__device__ __forceinline__ unsigned int float_key(float f) {
    unsigned int u = __float_as_uint(f);
    return (u & 0x80000000u) ? ~u : (u | 0x80000000u);
}
__device__ __forceinline__ void mma_bf16(float* d, const uint32_t* a, const uint32_t* b) {
    asm volatile(
        "mma.sync.aligned.m16n8k16.row.col.f32.bf16.bf16.f32 "
        "{%0,%1,%2,%3}, {%4,%5,%6,%7}, {%8,%9}, {%0,%1,%2,%3};"
        : "+f"(d[0]), "+f"(d[1]), "+f"(d[2]), "+f"(d[3])
        : "r"(a[0]), "r"(a[1]), "r"(a[2]), "r"(a[3]), "r"(b[0]), "r"(b[1]));
}
__device__ __forceinline__ unsigned int pack_bf16x2(float lo, float hi) {
    __nv_bfloat162 h = __floats2bfloat162_rn(lo, hi);
    return *reinterpret_cast<unsigned int*>(&h);
}

// ---------------------------------------------------------------------------
// init: warp-per-row; emb->bf16 (coalesced), inv-norm via warp reduce, amax=0
// ---------------------------------------------------------------------------
__global__ void __launch_bounds__(256)
init_kernel(const float* __restrict__ emb) {
    const int warp = threadIdx.x >> 5, lane = threadIdx.x & 31;
    const int row  = blockIdx.x * 8 + warp;
    const float4* p = reinterpret_cast<const float4*>(emb + (size_t)row * LATENT_DIM);
    float4 a = p[lane * 2], b = p[lane * 2 + 1];
    uint4 o;
    o.x = pack_bf16x2(a.x, a.y); o.y = pack_bf16x2(a.z, a.w);
    o.z = pack_bf16x2(b.x, b.y); o.w = pack_bf16x2(b.z, b.w);
    *reinterpret_cast<uint4*>(g_emb_bf16 + (size_t)row * LATENT_DIM + lane * 8) = o;
    float s = a.x*a.x + a.y*a.y + a.z*a.z + a.w*a.w
            + b.x*b.x + b.y*b.y + b.z*b.z + b.w*b.w;
    #pragma unroll
    for (int off = 16; off > 0; off >>= 1) s += __shfl_xor_sync(0xFFFFFFFFu, s, off);
    if (lane == 0) {
        g_inv_norm[row] = rsqrtf(s);
        g_amax[row] = 0u;                              // NUM_EMB == BATCH == 8192
    }
}

// z (fp32 ptr) -> g_z_bf16 + per-row 1/|z|  (warp per row)
__global__ void __launch_bounds__(256)
convert_z_kernel(const float* __restrict__ z) {
    const int warp = threadIdx.x >> 5, lane = threadIdx.x & 31;
    const int row  = blockIdx.x * 8 + warp;
    const float4* p = reinterpret_cast<const float4*>(z + (size_t)row * LATENT_DIM);
    float4 a = p[lane * 2], b = p[lane * 2 + 1];
    uint4 o;
    o.x = pack_bf16x2(a.x, a.y); o.y = pack_bf16x2(a.z, a.w);
    o.z = pack_bf16x2(b.x, b.y); o.w = pack_bf16x2(b.z, b.w);
    *reinterpret_cast<uint4*>(g_z_bf16 + (size_t)row * LATENT_DIM + lane * 8) = o;
    float s = a.x*a.x + a.y*a.y + a.z*a.z + a.w*a.w
            + b.x*b.x + b.y*b.y + b.z*b.z + b.w*b.w;
    #pragma unroll
    for (int off = 16; off > 0; off >>= 1) s += __shfl_xor_sync(0xFFFFFFFFu, s, off);
    if (lane == 0) g_zinv[row] = rsqrtf(s);
}

// ---------------------------------------------------------------------------
// fp32 SIMT GEMM (encoder + decoder): C = A[M,K] @ B[N,K]^T + bias
// ---------------------------------------------------------------------------
constexpr int BM = 128, BN = 128, BK = 16, TM = 8, TN = 8;
constexpr int BMP = 132;
constexpr int NTHREADS = 256;

__device__ __forceinline__ void load_tile(const float* __restrict__ src, int ld,
                                          int row0, int k0,
                                          float* __restrict__ dst, int tid) {
    #pragma unroll
    for (int it = 0; it < 2; it++) {
        int idx = tid + it * NTHREADS;
        int r   = idx >> 2;
        int kq  = (idx & 3) * 4;
        float4 v = *reinterpret_cast<const float4*>(&src[(size_t)(row0 + r) * ld + k0 + kq]);
        dst[(kq + 0) * BMP + r] = v.x;
        dst[(kq + 1) * BMP + r] = v.y;
        dst[(kq + 2) * BMP + r] = v.z;
        dst[(kq + 3) * BMP + r] = v.w;
    }
}

__global__ void __launch_bounds__(NTHREADS)
sgemm_abT_bias(const float* __restrict__ A, const float* __restrict__ B,
               const float* __restrict__ bias, float* __restrict__ C,
               int M, int N, int K) {
    __shared__ __align__(16) float As[BK * BMP];
    __shared__ __align__(16) float Bs[BK * BMP];
    const int tid  = threadIdx.x;
    const int tx   = tid & 15;
    const int ty   = tid >> 4;
    const int row0 = blockIdx.y * BM;
    const int col0 = blockIdx.x * BN;
    float acc[TM][TN] = {};
    for (int k0 = 0; k0 < K; k0 += BK) {
        load_tile(A, K, row0, k0, As, tid);
        load_tile(B, K, col0, k0, Bs, tid);
        __syncthreads();
        #pragma unroll
        for (int kk = 0; kk < BK; kk++) {
            float rm[TM], rn[TN];
            float4 a0 = *reinterpret_cast<const float4*>(&As[kk * BMP + ty * TM]);
            float4 a1 = *reinterpret_cast<const float4*>(&As[kk * BMP + ty * TM + 4]);
            float4 b0 = *reinterpret_cast<const float4*>(&Bs[kk * BMP + tx * TN]);
            float4 b1 = *reinterpret_cast<const float4*>(&Bs[kk * BMP + tx * TN + 4]);
            rm[0]=a0.x; rm[1]=a0.y; rm[2]=a0.z; rm[3]=a0.w;
            rm[4]=a1.x; rm[5]=a1.y; rm[6]=a1.z; rm[7]=a1.w;
            rn[0]=b0.x; rn[1]=b0.y; rn[2]=b0.z; rn[3]=b0.w;
            rn[4]=b1.x; rn[5]=b1.y; rn[6]=b1.z; rn[7]=b1.w;
            #pragma unroll
            for (int m = 0; m < TM; m++)
                #pragma unroll
                for (int n = 0; n < TN; n++)
                    acc[m][n] = fmaf(rm[m], rn[n], acc[m][n]);
        }
        __syncthreads();
    }
    #pragma unroll
    for (int m = 0; m < TM; m++) {
        int r = row0 + ty * TM + m;
        #pragma unroll
        for (int n = 0; n < TN; n += 4) {
            int c = col0 + tx * TN + n;
            float4 v;
            v.x = acc[m][n + 0] + bias[c + 0];
            v.y = acc[m][n + 1] + bias[c + 1];
            v.z = acc[m][n + 2] + bias[c + 2];
            v.w = acc[m][n + 3] + bias[c + 3];
            *reinterpret_cast<float4*>(&C[(size_t)r * N + c]) = v;
        }
    }
}

// ---------------------------------------------------------------------------
// HMMA bf16 score GEMM (direct-LDS fragments). CTA 128x128, 8 warps, K chunks 64.
// Scores are TRUE cosines: acc * inv_norm[col] * zinv[row].
// ---------------------------------------------------------------------------
constexpr int SKH = 72;

__device__ __forceinline__ void hmma_load_chunk(const __nv_bfloat16* __restrict__ g,
                                                int gr0, int k0, __nv_bfloat16* sm, int tid) {
    #pragma unroll
    for (int it = 0; it < 4; it++) {
        int idx = tid + it * 256;
        int r   = idx >> 3;
        int c   = idx & 7;
        *reinterpret_cast<uint4*>(&sm[r * SKH + c * 8]) =
            *reinterpret_cast<const uint4*>(g + (size_t)(gr0 + r) * 256 + k0 + c * 8);
    }
}

__global__ void __launch_bounds__(256)
hmma_scores_kernel() {
    __shared__ __align__(16) __nv_bfloat16 sA[128 * SKH];
    __shared__ __align__(16) __nv_bfloat16 sB[128 * SKH];
    __shared__ float s_inv[128];
    __shared__ float s_zinv[128];
    __shared__ unsigned int s_amax[128];

    const int tid = threadIdx.x, wid = tid >> 5, lane = tid & 31;
    const int row0 = blockIdx.y * 128, col0 = blockIdx.x * 128;
    const int wm = (wid & 3) * 32, wn = (wid >> 2) * 64;
    const int g = lane >> 2, q = lane & 3;

    if (tid < 128) {
        s_inv[tid]  = g_inv_norm[col0 + tid];
        s_zinv[tid] = g_zinv[row0 + tid];
        s_amax[tid] = 0u;
    }

    float acc[2][8][4] = {};
    #pragma unroll
    for (int kc = 0; kc < 4; kc++) {
        hmma_load_chunk(g_z_bf16, row0, kc * 64, sA, tid);
        hmma_load_chunk(g_emb_bf16, col0, kc * 64, sB, tid);
        __syncthreads();
        #pragma unroll
        for (int k16 = 0; k16 < 4; k16++) {
            const int koff = k16 * 16 + q * 2;
            uint32_t a[2][4];
            #pragma unroll
            for (int mf = 0; mf < 2; mf++) {
                const __nv_bfloat16* base = &sA[(wm + mf * 16 + g) * SKH + koff];
                a[mf][0] = *reinterpret_cast<const uint32_t*>(base);
                a[mf][1] = *reinterpret_cast<const uint32_t*>(base + 8 * SKH);
                a[mf][2] = *reinterpret_cast<const uint32_t*>(base + 8);
                a[mf][3] = *reinterpret_cast<const uint32_t*>(base + 8 * SKH + 8);
            }
            uint32_t b[8][2];
            #pragma unroll
            for (int nf = 0; nf < 8; nf++) {
                const __nv_bfloat16* nb = &sB[(wn + nf * 8 + g) * SKH + koff];
                b[nf][0] = *reinterpret_cast<const uint32_t*>(nb);
                b[nf][1] = *reinterpret_cast<const uint32_t*>(nb + 8);
            }
            #pragma unroll
            for (int mf = 0; mf < 2; mf++)
                #pragma unroll
                for (int nf = 0; nf < 8; nf++)
                    mma_bf16(acc[mf][nf], a[mf], b[nf]);
        }
        __syncthreads();
    }

    #pragma unroll
    for (int mf = 0; mf < 2; mf++) {
        #pragma unroll
        for (int rp = 0; rp < 2; rp++) {
            int lrow = wm + mf * 16 + g + rp * 8;
            int grow = row0 + lrow;
            float zi = s_zinv[lrow];
            unsigned int bestk = 0u;
            unsigned int* out = reinterpret_cast<unsigned int*>(
                g_scores + (size_t)grow * NUM_EMB + col0);
            #pragma unroll
            for (int nf = 0; nf < 8; nf++) {
                int lcol = wn + nf * 8 + q * 2;
                float s0 = acc[mf][nf][rp * 2 + 0] * s_inv[lcol + 0] * zi;
                float s1 = acc[mf][nf][rp * 2 + 1] * s_inv[lcol + 1] * zi;
                unsigned int k0 = float_key(s0), k1 = float_key(s1);
                bestk = bestk > k0 ? bestk : k0;
                bestk = bestk > k1 ? bestk : k1;
                out[lcol >> 1] = pack_bf16x2(s0, s1);
            }
            atomicMax(&s_amax[lrow], bestk);
        }
    }
    __syncthreads();
    if (tid < 128) atomicMax(&g_amax[row0 + tid], s_amax[tid]);
}

// ---------------------------------------------------------------------------
// select: warp-per-row, rolled scan, warp-cooperative exact rescore + gather
// ---------------------------------------------------------------------------
__global__ void __launch_bounds__(256)
select_gather_kernel(const float* __restrict__ z, const float* __restrict__ emb,
                     float* __restrict__ zq_out, float* __restrict__ idx_out) {
    const int warp = threadIdx.x >> 5, lane = threadIdx.x & 31;
    const int row  = blockIdx.x * 8 + warp;

    // per-lane z fragment: elems [lane*8, lane*8+8)
    const float4* zrow = reinterpret_cast<const float4*>(z + (size_t)row * LATENT_DIM);
    float4 zf0 = zrow[lane * 2], zf1 = zrow[lane * 2 + 1];

    unsigned int mk = g_amax[row];
    float maxf = (mk & 0x80000000u) ? __uint_as_float(mk ^ 0x80000000u)
                                    : __uint_as_float(~mk);
    float thresh = maxf - MARGIN;
    // true cosines: thresh must be in [-1-eps, 1]; otherwise safety full-scan
    if (!(thresh >= -4.0f) || !(thresh <= 1.0f)) thresh = -4.0f;

    unsigned long long best = 0ull;
    const uint4* srow = reinterpret_cast<const uint4*>(g_scores + (size_t)row * NUM_EMB);

    for (int it = 0; it < 32; it++) {                 // 32 x (32 lanes x 8 scores)
        uint4 v = srow[it * 32 + lane];
        unsigned int w[4] = {v.x, v.y, v.z, v.w};
        unsigned int cmask = 0;
        #pragma unroll
        for (int qq = 0; qq < 4; qq++) {
            __nv_bfloat162 h = *reinterpret_cast<__nv_bfloat162*>(&w[qq]);
            if (!(__bfloat162float(h.x) < thresh)) cmask |= 1u << (2 * qq);
            if (!(__bfloat162float(h.y) < thresh)) cmask |= 1u << (2 * qq + 1);
        }
        unsigned int lmask = __ballot_sync(0xFFFFFFFFu, cmask != 0);
        while (lmask) {                                // rare: ~2-3 candidates per row
            int src = __ffs(lmask) - 1; lmask &= lmask - 1;
            unsigned int cm = __shfl_sync(0xFFFFFFFFu, cmask, src);
            while (cm) {
                int j = __ffs(cm) - 1; cm &= cm - 1;
                int k = it * 256 + src * 8 + j;
                // warp-cooperative exact fp32 dot
                const float4* e = reinterpret_cast<const float4*>(emb + (size_t)k * LATENT_DIM);
                float4 e0 = e[lane * 2], e1 = e[lane * 2 + 1];
                float d = e0.x*zf0.x + e0.y*zf0.y + e0.z*zf0.z + e0.w*zf0.w
                        + e1.x*zf1.x + e1.y*zf1.y + e1.z*zf1.z + e1.w*zf1.w;
                #pragma unroll
                for (int off = 16; off > 0; off >>= 1)
                    d += __shfl_xor_sync(0xFFFFFFFFu, d, off);
                float cosv = d * g_inv_norm[k];        // identical on all lanes
                unsigned long long key =
                    ((unsigned long long)float_key(cosv) << 32) |
                    (unsigned long long)(0xFFFFFFFFu - (unsigned)k);
                best = best > key ? best : key;
            }
        }
    }
    unsigned int widx = 0xFFFFFFFFu - (unsigned int)(best & 0xFFFFFFFFull);
    if (widx >= NUM_EMB) widx = 0;                     // never wild-read
    if (lane == 0) idx_out[row] = (float)widx;
    const float4* e = reinterpret_cast<const float4*>(emb + (size_t)widx * LATENT_DIM);
    float4* dst = reinterpret_cast<float4*>(zq_out + (size_t)row * LATENT_DIM);
    dst[lane * 2]     = e[lane * 2];
    dst[lane * 2 + 1] = e[lane * 2 + 1];
}

// ---------------------------------------------------------------------------
// launch
// ---------------------------------------------------------------------------
extern "C" void kernel_launch(void* const* d_in, const int* in_sizes, int n_in,
                              void* d_out, int out_size) {
    const float* x     = (const float*)d_in[0];
    const float* enc_w = (const float*)d_in[1];
    const float* enc_b = (const float*)d_in[2];
    const float* emb   = (const float*)d_in[3];
    const float* dec_w = (const float*)d_in[4];
    const float* dec_b = (const float*)d_in[5];

    float* out     = (float*)d_out;
    float* x_recon = out;
    float* z       = x_recon + (size_t)BATCH * INPUT_DIM;
    float* zq      = z + (size_t)BATCH * LATENT_DIM;
    float* idxf    = zq + (size_t)BATCH * LATENT_DIM;

    // 0) inv-norms + emb bf16 + amax reset
    init_kernel<<<NUM_EMB / 8, 256>>>(emb);

    // 1) encoder (fp32 SIMT): z = x @ enc_w^T + enc_b
    sgemm_abT_bias<<<dim3(LATENT_DIM / BN, BATCH / BM), NTHREADS>>>(
        x, enc_w, enc_b, z, BATCH, LATENT_DIM, INPUT_DIM);

    // 2) z -> bf16 + per-row 1/|z|
    convert_z_kernel<<<BATCH / 8, 256>>>(z);

    // 3) HMMA bf16 approximate cosine scores + per-row approx max
    hmma_scores_kernel<<<dim3(NUM_EMB / 128, BATCH / 128), 256>>>();

    // 4) candidate select + exact fp32 rescore + argmin + gather
    select_gather_kernel<<<BATCH / 8, 256>>>(z, emb, zq, idxf);

    // 5) decoder (fp32 SIMT): x_recon = z_q @ dec_w^T + dec_b
    sgemm_abT_bias<<<dim3(INPUT_DIM / BN, BATCH / BM), NTHREADS>>>(
        zq, dec_w, dec_b, x_recon, BATCH, INPUT_DIM, LATENT_DIM);
}